// round 4
// baseline (speedup 1.0000x reference)
#include <cuda_runtime.h>

// ---------------------------------------------------------------------------
// Round 2: weight-stationary hidden-split LSTM + packed f32x2 FMA.
//
// Grid = 8 batch-groups x 16 hidden-slices = 128 CTAs (all co-resident,
// 1 CTA/SM forced by smem). Each CTA keeps its 384x64 W slice in smem for the
// whole sequence (zero per-step L2 weight traffic). Per step, the 16 CTAs of
// a batch group exchange h slices via a double-buffered global buffer and a
// sense-reversing group barrier (512 barriers/launch — even, so the
// persistent sense flag returns to its initial state across graph replays).
// Gate GEMM uses fma.rn.f32x2 (2 MACs/instr) -> fp32 full-rate per SM.
// ---------------------------------------------------------------------------

#define SEQ     512
#define BATCH   512
#define INPUT   128
#define HIDDEN  256
#define KTOT    (INPUT + HIDDEN)   // 384
#define BT      64                 // batch rows per CTA
#define HS      16                 // hidden units per CTA
#define NGROUP  (BATCH / BT)       // 8
#define NSLICE  (HIDDEN / HS)      // 16
#define NCTA    (NGROUP * NSLICE)  // 128
#define NTHR    256
#define LCOLS   (4 * HS)           // 64 local gate columns
#define XH_LD   388                // padded xh row stride (floats)
#define GLD     68                 // padded gate-staging row stride

#define SMEM_FLOATS (KTOT * LCOLS + BT * XH_LD + BT * GLD)
#define SMEM_BYTES  (SMEM_FLOATS * 4)   // 215040 B

// Cross-CTA h exchange (double buffered) + group barrier state.
__device__ float g_h[2][NGROUP][BT][HIDDEN];
__device__ int   g_bar_count[NGROUP];
__device__ int   g_bar_sense[NGROUP];

// ---------------------------------------------------------------------------
__device__ __forceinline__ unsigned long long splat2(float v) {
    unsigned long long r;
    asm("mov.b64 %0, {%1, %1};" : "=l"(r) : "f"(v));
    return r;
}
__device__ __forceinline__ unsigned long long pack2(float a, float b) {
    unsigned long long r;
    asm("mov.b64 %0, {%1, %2};" : "=l"(r) : "f"(a), "f"(b));
    return r;
}
__device__ __forceinline__ float2 unpack2(unsigned long long u) {
    float2 f;
    asm("mov.b64 {%0, %1}, %2;" : "=f"(f.x), "=f"(f.y) : "l"(u));
    return f;
}
__device__ __forceinline__ unsigned long long fma2(unsigned long long a,
                                                   unsigned long long b,
                                                   unsigned long long c) {
    unsigned long long d;
    asm("fma.rn.f32x2 %0, %1, %2, %3;" : "=l"(d) : "l"(a), "l"(b), "l"(c));
    return d;
}

__device__ __forceinline__ float sigf(float v) {
    return 1.0f / (1.0f + __expf(-v));
}
__device__ __forceinline__ float tanh_fast(float v) {
    return 2.0f / (1.0f + __expf(-2.0f * v)) - 1.0f;
}

// ---------------------------------------------------------------------------
__global__ void __launch_bounds__(NTHR, 1)
lstm_kernel(const float* __restrict__ x,
            const float* __restrict__ W_ih,
            const float* __restrict__ W_hh,
            const float* __restrict__ b_ih,
            const float* __restrict__ b_hh,
            const float* __restrict__ W_out,
            const float* __restrict__ b_out,
            float* __restrict__ out) {
    extern __shared__ float sm[];
    float* Wsm = sm;                        // [KTOT][LCOLS]
    float* xh  = Wsm + KTOT * LCOLS;        // [BT][XH_LD]: [0:128)=x, [128:384)=h
    float* gsm = xh + BT * XH_LD;           // [BT][GLD] gate staging

    const int tid   = threadIdx.x;
    const int g     = blockIdx.x >> 4;      // batch group
    const int slice = blockIdx.x & 15;      // hidden slice
    const int bb    = g * BT;

    // ---- one-time: load W slice transposed into smem -----------------------
    // local col c (0..63): gate type gt=c>>4, unit=c&15 -> global gate col.
    for (int i = tid; i < KTOT * LCOLS; i += NTHR) {
        int c = i / KTOT;
        int k = i - c * KTOT;
        int gcol = (c >> 4) * HIDDEN + slice * HS + (c & 15);
        float w = (k < INPUT) ? W_ih[(size_t)gcol * INPUT + k]
                              : W_hh[(size_t)gcol * HIDDEN + (k - INPUT)];
        Wsm[k * LCOLS + c] = w;
    }
    // zero xh (h region must start at 0)
    for (int i = tid; i < BT * XH_LD; i += NTHR) xh[i] = 0.0f;

    // ---- per-thread gate-GEMM tile: rows r0..r0+3, cols c4..c4+3 -----------
    const int r0 = (tid >> 4) * 4;
    const int c4 = (tid & 15) * 4;
    const int gcol0 = (c4 >> 4) * HIDDEN + slice * HS + (c4 & 15);
    const unsigned long long Blo = pack2(b_ih[gcol0 + 0] + b_hh[gcol0 + 0],
                                         b_ih[gcol0 + 1] + b_hh[gcol0 + 1]);
    const unsigned long long Bhi = pack2(b_ih[gcol0 + 2] + b_hh[gcol0 + 2],
                                         b_ih[gcol0 + 3] + b_hh[gcol0 + 3]);
    const float* xr0 = &xh[(r0 + 0) * XH_LD];
    const float* xr1 = &xh[(r0 + 1) * XH_LD];
    const float* xr2 = &xh[(r0 + 2) * XH_LD];
    const float* xr3 = &xh[(r0 + 3) * XH_LD];

    // ---- per-thread cell state: row rr, hidden units u0..u0+3 --------------
    const int rr = tid >> 2;
    const int u0 = (tid & 3) * 4;
    float c0 = 0.0f, c1 = 0.0f, c2 = 0.0f, c3 = 0.0f;

    int sense = 1;
    __syncthreads();   // Wsm + xh ready

    for (int s = 0; s < SEQ; ++s) {
        // ---- stage x_t rows (coalesced) ----
        const float4* xs = reinterpret_cast<const float4*>(
            x + ((size_t)s * BATCH + bb) * INPUT);
        for (int i = tid; i < BT * INPUT / 4; i += NTHR) {
            float4 v = xs[i];
            int r = i >> 5, cc = (i & 31) * 4;
            *reinterpret_cast<float4*>(&xh[r * XH_LD + cc]) = v;
        }
        // ---- stage full h(s-1) from the exchange buffer ----
        if (s > 0) {
            const float4* hs = reinterpret_cast<const float4*>(
                &g_h[(s - 1) & 1][g][0][0]);
            for (int i = tid; i < BT * HIDDEN / 4; i += NTHR) {
                float4 v = hs[i];
                int r = i >> 6, cc = (i & 63) * 4;
                *reinterpret_cast<float4*>(&xh[r * XH_LD + INPUT + cc]) = v;
            }
        }
        __syncthreads();

        // ---- gates = bias + xh @ Wslice (4 rows x 4 cols, packed f32x2) ----
        unsigned long long A00 = Blo, A01 = Bhi, A10 = Blo, A11 = Bhi;
        unsigned long long A20 = Blo, A21 = Bhi, A30 = Blo, A31 = Bhi;
        #pragma unroll 4
        for (int k4 = 0; k4 < KTOT / 4; ++k4) {
            const int kb = 4 * k4;
            ulonglong2 wa = *reinterpret_cast<const ulonglong2*>(&Wsm[(kb + 0) * LCOLS + c4]);
            ulonglong2 wb = *reinterpret_cast<const ulonglong2*>(&Wsm[(kb + 1) * LCOLS + c4]);
            ulonglong2 wc = *reinterpret_cast<const ulonglong2*>(&Wsm[(kb + 2) * LCOLS + c4]);
            ulonglong2 wd = *reinterpret_cast<const ulonglong2*>(&Wsm[(kb + 3) * LCOLS + c4]);
            float4 h0 = *reinterpret_cast<const float4*>(xr0 + kb);
            float4 h1 = *reinterpret_cast<const float4*>(xr1 + kb);
            float4 h2 = *reinterpret_cast<const float4*>(xr2 + kb);
            float4 h3 = *reinterpret_cast<const float4*>(xr3 + kb);
            unsigned long long v;
            v = splat2(h0.x); A00 = fma2(v, wa.x, A00); A01 = fma2(v, wa.y, A01);
            v = splat2(h1.x); A10 = fma2(v, wa.x, A10); A11 = fma2(v, wa.y, A11);
            v = splat2(h2.x); A20 = fma2(v, wa.x, A20); A21 = fma2(v, wa.y, A21);
            v = splat2(h3.x); A30 = fma2(v, wa.x, A30); A31 = fma2(v, wa.y, A31);
            v = splat2(h0.y); A00 = fma2(v, wb.x, A00); A01 = fma2(v, wb.y, A01);
            v = splat2(h1.y); A10 = fma2(v, wb.x, A10); A11 = fma2(v, wb.y, A11);
            v = splat2(h2.y); A20 = fma2(v, wb.x, A20); A21 = fma2(v, wb.y, A21);
            v = splat2(h3.y); A30 = fma2(v, wb.x, A30); A31 = fma2(v, wb.y, A31);
            v = splat2(h0.z); A00 = fma2(v, wc.x, A00); A01 = fma2(v, wc.y, A01);
            v = splat2(h1.z); A10 = fma2(v, wc.x, A10); A11 = fma2(v, wc.y, A11);
            v = splat2(h2.z); A20 = fma2(v, wc.x, A20); A21 = fma2(v, wc.y, A21);
            v = splat2(h3.z); A30 = fma2(v, wc.x, A30); A31 = fma2(v, wc.y, A31);
            v = splat2(h0.w); A00 = fma2(v, wd.x, A00); A01 = fma2(v, wd.y, A01);
            v = splat2(h1.w); A10 = fma2(v, wd.x, A10); A11 = fma2(v, wd.y, A11);
            v = splat2(h2.w); A20 = fma2(v, wd.x, A20); A21 = fma2(v, wd.y, A21);
            v = splat2(h3.w); A30 = fma2(v, wd.x, A30); A31 = fma2(v, wd.y, A31);
        }
        {
            float2 p, q;
            p = unpack2(A00); q = unpack2(A01);
            *reinterpret_cast<float4*>(&gsm[(r0 + 0) * GLD + c4]) = make_float4(p.x, p.y, q.x, q.y);
            p = unpack2(A10); q = unpack2(A11);
            *reinterpret_cast<float4*>(&gsm[(r0 + 1) * GLD + c4]) = make_float4(p.x, p.y, q.x, q.y);
            p = unpack2(A20); q = unpack2(A21);
            *reinterpret_cast<float4*>(&gsm[(r0 + 2) * GLD + c4]) = make_float4(p.x, p.y, q.x, q.y);
            p = unpack2(A30); q = unpack2(A31);
            *reinterpret_cast<float4*>(&gsm[(r0 + 3) * GLD + c4]) = make_float4(p.x, p.y, q.x, q.y);
        }
        __syncthreads();

        // ---- cell/hidden update for (row rr, units u0..u0+3) ----
        {
            float4 gi = *reinterpret_cast<const float4*>(&gsm[rr * GLD +  0 + u0]);
            float4 gf = *reinterpret_cast<const float4*>(&gsm[rr * GLD + 16 + u0]);
            float4 gg = *reinterpret_cast<const float4*>(&gsm[rr * GLD + 32 + u0]);
            float4 go = *reinterpret_cast<const float4*>(&gsm[rr * GLD + 48 + u0]);

            c0 = sigf(gf.x) * c0 + sigf(gi.x) * tanh_fast(gg.x);
            c1 = sigf(gf.y) * c1 + sigf(gi.y) * tanh_fast(gg.y);
            c2 = sigf(gf.z) * c2 + sigf(gi.z) * tanh_fast(gg.z);
            c3 = sigf(gf.w) * c3 + sigf(gi.w) * tanh_fast(gg.w);

            float4 hv;
            hv.x = sigf(go.x) * tanh_fast(c0);
            hv.y = sigf(go.y) * tanh_fast(c1);
            hv.z = sigf(go.z) * tanh_fast(c2);
            hv.w = sigf(go.w) * tanh_fast(c3);
            *reinterpret_cast<float4*>(&g_h[s & 1][g][rr][slice * HS + u0]) = hv;
        }
        __syncthreads();   // all h writes issued; gsm/xh reads for step s done

        // ---- sense-reversing group barrier (16 CTAs of this batch group) ----
        if (tid == 0) {
            __threadfence();                         // release h writes
            int prev = atomicAdd(&g_bar_count[g], 1);
            if (prev == NSLICE - 1) {
                atomicExch(&g_bar_count[g], 0);
                __threadfence();                     // reset visible before sense
                atomicExch(&g_bar_sense[g], sense);
            } else {
                volatile int* sp = &g_bar_sense[g];
                while (*sp != sense) __nanosleep(32);
                __threadfence();                     // acquire peers' h writes
            }
        }
        __syncthreads();
        sense ^= 1;
    }

    // ---- final projection (slice 0 of each group): out = h_n @ W_out + b ---
    if (slice == 0) {
        const int wid = tid >> 5, lane = tid & 31;
        const float bo = b_out[0];
        for (int r = wid; r < BT; r += 8) {
            const float* hr = &g_h[(SEQ - 1) & 1][g][r][0];
            float ssum = 0.0f;
            #pragma unroll
            for (int n = lane; n < HIDDEN; n += 32)
                ssum += hr[n] * W_out[n];
            #pragma unroll
            for (int off = 16; off > 0; off >>= 1)
                ssum += __shfl_xor_sync(0xFFFFFFFFu, ssum, off);
            if (lane == 0) out[bb + r] = ssum + bo;
        }
    }
}

// ---------------------------------------------------------------------------
extern "C" void kernel_launch(void* const* d_in, const int* in_sizes, int n_in,
                              void* d_out, int out_size) {
    const float* x     = (const float*)d_in[0];
    const float* W_ih  = (const float*)d_in[1];
    const float* W_hh  = (const float*)d_in[2];
    const float* b_ih  = (const float*)d_in[3];
    const float* b_hh  = (const float*)d_in[4];
    const float* W_out = (const float*)d_in[5];
    const float* b_out = (const float*)d_in[6];
    float* out = (float*)d_out;

    cudaFuncSetAttribute(lstm_kernel,
                         cudaFuncAttributeMaxDynamicSharedMemorySize, SMEM_BYTES);
    lstm_kernel<<<NCTA, NTHR, SMEM_BYTES>>>(x, W_ih, W_hh, b_ih, b_hh,
                                            W_out, b_out, out);
}

// round 6
// speedup vs baseline: 1.7494x; 1.7494x over previous
#include <cuda_runtime.h>
#include <cuda_bf16.h>
#include <cstdint>

// ---------------------------------------------------------------------------
// LSTM via warp-level mma.sync (bf16, fp32 accum) with bf16-split emulation.
// tcgen05 is unavailable (harness targets compute_100), so we use the base-ISA
// HMMA path: mma.sync.aligned.m16n8k16.row.col.f32.bf16.bf16.f32 + ldmatrix.
//
// Grid: 8 batch groups (M=64) x 16 slices (N=64 = 16 hidden units x 4 gates)
//     = 128 CTAs, 1/SM. Per warp: M=32, N=16, K=384. B_hi (weights) lives in
//     96 registers for the whole sequence; B_lo read per step via ldmatrix;
//     A = [x|h] hi+lo staged in smem per step. 3 MMA passes emulate fp32:
//     A_hi*B_hi + A_lo*B_hi + A_hi*B_lo  (err ~2^-16 per product).
// h exchanged between the 16 slice-CTAs of a group through L2 (double
// buffered, bf16 hi/lo planes) + sense-reversing barrier (512 = even).
// ---------------------------------------------------------------------------

#define SEQ     512
#define BATCH   512
#define INPUT   128
#define HIDDEN  256
#define NGROUP  8
#define NSLICE  16
#define NCTA    128
#define NTHR    256
#define MR      64          // batch rows per CTA
#define NC      64          // gate cols per CTA (4 gates x 16 units)
#define KTOT    384

// smem layout (bytes); A/B pitch = 392 bf16 = 784 B (conflict-free ldmatrix)
#define PITCH   784
#define AHI     0
#define ALO     50176
#define BHI     100352
#define BLO     150528
#define GSMO    200704       // gate staging [64][72] f32
#define GPITCH  72
#define SMEM_BYTES 219136

// Exchange / scratch (static device globals — no runtime allocation).
__device__ __align__(16) __nv_bfloat16 g_xhi[SEQ * BATCH * INPUT];
__device__ __align__(16) __nv_bfloat16 g_xlo[SEQ * BATCH * INPUT];
__device__ __align__(16) __nv_bfloat16 g_hh[2][NGROUP][MR][HIDDEN];
__device__ __align__(16) __nv_bfloat16 g_hl[2][NGROUP][MR][HIDDEN];
__device__ int g_bar_count[NGROUP];
__device__ int g_bar_sense[NGROUP];

// ---------------------------------------------------------------------------
__device__ __forceinline__ uint32_t smem_u32(const void* p) {
    uint32_t a;
    asm("{ .reg .u64 t; cvta.to.shared.u64 t, %1; cvt.u32.u64 %0, t; }"
        : "=r"(a) : "l"(p));
    return a;
}
__device__ __forceinline__ void ldsm4(uint32_t* r, uint32_t addr) {
    asm volatile("ldmatrix.sync.aligned.m8n8.x4.shared.b16 {%0,%1,%2,%3}, [%4];"
        : "=r"(r[0]), "=r"(r[1]), "=r"(r[2]), "=r"(r[3]) : "r"(addr));
}
__device__ __forceinline__ void ldsm2(uint32_t* r, uint32_t addr) {
    asm volatile("ldmatrix.sync.aligned.m8n8.x2.shared.b16 {%0,%1}, [%2];"
        : "=r"(r[0]), "=r"(r[1]) : "r"(addr));
}
__device__ __forceinline__ void mma_bf16(float* d, const uint32_t* a,
                                         const uint32_t* b) {
    asm volatile("mma.sync.aligned.m16n8k16.row.col.f32.bf16.bf16.f32 "
        "{%0,%1,%2,%3}, {%4,%5,%6,%7}, {%8,%9}, {%0,%1,%2,%3};"
        : "+f"(d[0]), "+f"(d[1]), "+f"(d[2]), "+f"(d[3])
        : "r"(a[0]), "r"(a[1]), "r"(a[2]), "r"(a[3]), "r"(b[0]), "r"(b[1]));
}
__device__ __forceinline__ float sigf(float v)  { return 1.0f / (1.0f + __expf(-v)); }
__device__ __forceinline__ float tanhx(float v) { return 2.0f / (1.0f + __expf(-2.0f * v)) - 1.0f; }
__device__ __forceinline__ uint32_t pk2(float a, float b) {
    __nv_bfloat162 t = __floats2bfloat162_rn(a, b);
    return *reinterpret_cast<uint32_t*>(&t);
}

// ---------------------------------------------------------------------------
// Prep: split x into bf16 hi/lo planes (same row-major layout as x).
// ---------------------------------------------------------------------------
__global__ void prep_x(const float* __restrict__ x) {
    const int N4 = SEQ * BATCH * INPUT / 4;
    for (int i = blockIdx.x * blockDim.x + threadIdx.x; i < N4;
         i += gridDim.x * blockDim.x) {
        float4 v = *reinterpret_cast<const float4*>(x + 4 * i);
        float hx = __bfloat162float(__float2bfloat16(v.x));
        float hy = __bfloat162float(__float2bfloat16(v.y));
        float hz = __bfloat162float(__float2bfloat16(v.z));
        float hw = __bfloat162float(__float2bfloat16(v.w));
        uint2 hi, lo;
        hi.x = pk2(v.x, v.y); hi.y = pk2(v.z, v.w);
        lo.x = pk2(v.x - hx, v.y - hy); lo.y = pk2(v.z - hz, v.w - hw);
        reinterpret_cast<uint2*>(g_xhi)[i] = hi;
        reinterpret_cast<uint2*>(g_xlo)[i] = lo;
    }
}

// ---------------------------------------------------------------------------
__global__ void __launch_bounds__(NTHR, 1)
lstm_mma(const float* __restrict__ W_ih, const float* __restrict__ W_hh,
         const float* __restrict__ b_ih, const float* __restrict__ b_hh,
         const float* __restrict__ W_out, const float* __restrict__ b_out,
         float* __restrict__ out) {
    extern __shared__ char smem[];
    const uint32_t sA = smem_u32(smem);
    float* gsmf = reinterpret_cast<float*>(smem + GSMO);

    const int tid  = threadIdx.x;
    const int wid  = tid >> 5;
    const int lane = tid & 31;
    const int g     = blockIdx.x >> 4;     // batch group (M rows g*64..)
    const int slice = blockIdx.x & 15;     // 16 hidden units slice*16..

    // warp tile: mq = M-half (32 rows), nq = N-quarter (16 cols)
    const int mq = wid & 1;
    const int nq = wid >> 1;

    // ---- build B (weights) hi/lo in smem: Bsm[n][k], n = CTA gate col ----
    for (int i = tid; i < NC * KTOT; i += NTHR) {
        int n = i / KTOT, k = i - n * KTOT;
        int gcol = (n >> 4) * HIDDEN + slice * 16 + (n & 15);
        float wv = (k < INPUT) ? W_ih[(size_t)gcol * INPUT + k]
                               : W_hh[(size_t)gcol * HIDDEN + (k - INPUT)];
        __nv_bfloat16 bh = __float2bfloat16(wv);
        __nv_bfloat16 bl = __float2bfloat16(wv - __bfloat162float(bh));
        *reinterpret_cast<__nv_bfloat16*>(smem + BHI + n * PITCH + 2 * k) = bh;
        *reinterpret_cast<__nv_bfloat16*>(smem + BLO + n * PITCH + 2 * k) = bl;
    }
    // zero A planes (h region must be 0 for step 0)
    for (int i = tid; i < 2 * ALO / 4; i += NTHR)
        reinterpret_cast<uint32_t*>(smem + AHI)[i] = 0;
    __syncthreads();

    // ---- ldmatrix lane addresses ----
    const int l15 = lane & 15;
    const uint32_t aHi = sA + AHI + (uint32_t)(32 * mq + (lane & 15)) * PITCH
                       + (uint32_t)(lane >> 4) * 16;
    const uint32_t aLo = aHi + (ALO - AHI);
    const uint32_t bHiA = sA + BHI + (uint32_t)(16 * nq + (l15 & 7)) * PITCH
                        + (uint32_t)((l15 >> 3) & 1) * 16;
    const uint32_t bLoA = bHiA + (BLO - BHI);

    // ---- B_hi resident in registers: 24 k-tiles x 2 n-tiles x 2 regs ----
    uint32_t bh[24][2][2];
    #pragma unroll
    for (int kt = 0; kt < 24; ++kt) {
        ldsm2(&bh[kt][0][0], bHiA + kt * 32);
        ldsm2(&bh[kt][1][0], bHiA + 8 * PITCH + kt * 32);
    }

    // ---- bias (C init): cols of this thread's C fragments ----
    float cb[2][2];
    #pragma unroll
    for (int nt = 0; nt < 2; ++nt) {
        int c0 = 16 * nq + 8 * nt + 2 * (lane & 3);
        int gc0 = (c0 >> 4) * HIDDEN + slice * 16 + (c0 & 15);
        int c1 = c0 + 1;
        int gc1 = (c1 >> 4) * HIDDEN + slice * 16 + (c1 & 15);
        cb[nt][0] = b_ih[gc0] + b_hh[gc0];
        cb[nt][1] = b_ih[gc1] + b_hh[gc1];
    }

    // ---- per-thread cell state: row r = tid>>2, units u0..u0+3 ----
    const int er = tid >> 2;
    const int u0 = (tid & 3) * 4;
    float cst[4] = {0.f, 0.f, 0.f, 0.f};
    int sense = 1;

    const uint4* xhi4 = reinterpret_cast<const uint4*>(g_xhi);
    const uint4* xlo4 = reinterpret_cast<const uint4*>(g_xlo);

    for (int s = 0; s < SEQ; ++s) {
        // ======== stage A = [x|h] (hi+lo) into smem, row-major ========
        {   // x: 64 rows x 16 uint4 chunks (cols 0..127)
            size_t xb = ((size_t)s * BATCH + g * MR) * INPUT / 8;
            for (int i = tid; i < MR * 16; i += NTHR) {
                int r = i >> 4, ch = i & 15;
                uint4 vh = __ldg(&xhi4[xb + (size_t)r * 16 + ch]);
                uint4 vl = __ldg(&xlo4[xb + (size_t)r * 16 + ch]);
                *reinterpret_cast<uint4*>(smem + AHI + r * PITCH + ch * 16) = vh;
                *reinterpret_cast<uint4*>(smem + ALO + r * PITCH + ch * 16) = vl;
            }
        }
        if (s > 0) {   // h: 64 rows x 32 uint4 chunks (cols 128..383)
            const uint4* hh = reinterpret_cast<const uint4*>(&g_hh[(s - 1) & 1][g][0][0]);
            const uint4* hl = reinterpret_cast<const uint4*>(&g_hl[(s - 1) & 1][g][0][0]);
            for (int i = tid; i < MR * 32; i += NTHR) {
                int r = i >> 5, ch = i & 31;
                uint4 vh = __ldcg(&hh[r * 32 + ch]);
                uint4 vl = __ldcg(&hl[r * 32 + ch]);
                *reinterpret_cast<uint4*>(smem + AHI + r * PITCH + 256 + ch * 16) = vh;
                *reinterpret_cast<uint4*>(smem + ALO + r * PITCH + 256 + ch * 16) = vl;
            }
        }
        __syncthreads();

        // ======== gate GEMM: 3-pass bf16-split, K=384 ========
        float d[2][2][4];
        #pragma unroll
        for (int mt = 0; mt < 2; ++mt)
            #pragma unroll
            for (int nt = 0; nt < 2; ++nt) {
                d[mt][nt][0] = cb[nt][0]; d[mt][nt][1] = cb[nt][1];
                d[mt][nt][2] = cb[nt][0]; d[mt][nt][3] = cb[nt][1];
            }
        #pragma unroll
        for (int kt = 0; kt < 24; ++kt) {
            uint32_t ah0[4], ah1[4], al0[4], al1[4], bl0[2], bl1[2];
            ldsm4(ah0, aHi + kt * 32);
            ldsm4(ah1, aHi + 16 * PITCH + kt * 32);
            ldsm4(al0, aLo + kt * 32);
            ldsm4(al1, aLo + 16 * PITCH + kt * 32);
            ldsm2(bl0, bLoA + kt * 32);
            ldsm2(bl1, bLoA + 8 * PITCH + kt * 32);
            // A_hi * B_hi
            mma_bf16(d[0][0], ah0, bh[kt][0]); mma_bf16(d[0][1], ah0, bh[kt][1]);
            mma_bf16(d[1][0], ah1, bh[kt][0]); mma_bf16(d[1][1], ah1, bh[kt][1]);
            // A_lo * B_hi
            mma_bf16(d[0][0], al0, bh[kt][0]); mma_bf16(d[0][1], al0, bh[kt][1]);
            mma_bf16(d[1][0], al1, bh[kt][0]); mma_bf16(d[1][1], al1, bh[kt][1]);
            // A_hi * B_lo
            mma_bf16(d[0][0], ah0, bl0); mma_bf16(d[0][1], ah0, bl1);
            mma_bf16(d[1][0], ah1, bl0); mma_bf16(d[1][1], ah1, bl1);
        }
        // stage C frags to gsm [64][72]
        #pragma unroll
        for (int mt = 0; mt < 2; ++mt)
            #pragma unroll
            for (int nt = 0; nt < 2; ++nt) {
                int r0 = 32 * mq + 16 * mt + (lane >> 2);
                int c0 = 16 * nq + 8 * nt + 2 * (lane & 3);
                *reinterpret_cast<float2*>(&gsmf[r0 * GPITCH + c0]) =
                    make_float2(d[mt][nt][0], d[mt][nt][1]);
                *reinterpret_cast<float2*>(&gsmf[(r0 + 8) * GPITCH + c0]) =
                    make_float2(d[mt][nt][2], d[mt][nt][3]);
            }
        __syncthreads();

        // ======== epilogue: cell/hidden update (row er, units u0..u0+3) ====
        {
            float4 gi = *reinterpret_cast<const float4*>(&gsmf[er * GPITCH +  0 + u0]);
            float4 gf = *reinterpret_cast<const float4*>(&gsmf[er * GPITCH + 16 + u0]);
            float4 gg = *reinterpret_cast<const float4*>(&gsmf[er * GPITCH + 32 + u0]);
            float4 go = *reinterpret_cast<const float4*>(&gsmf[er * GPITCH + 48 + u0]);
            float hn[4];
            cst[0] = sigf(gf.x) * cst[0] + sigf(gi.x) * tanhx(gg.x);
            cst[1] = sigf(gf.y) * cst[1] + sigf(gi.y) * tanhx(gg.y);
            cst[2] = sigf(gf.z) * cst[2] + sigf(gi.z) * tanhx(gg.z);
            cst[3] = sigf(gf.w) * cst[3] + sigf(gi.w) * tanhx(gg.w);
            hn[0] = sigf(go.x) * tanhx(cst[0]);
            hn[1] = sigf(go.y) * tanhx(cst[1]);
            hn[2] = sigf(go.z) * tanhx(cst[2]);
            hn[3] = sigf(go.w) * tanhx(cst[3]);
            float h0 = __bfloat162float(__float2bfloat16(hn[0]));
            float h1 = __bfloat162float(__float2bfloat16(hn[1]));
            float h2 = __bfloat162float(__float2bfloat16(hn[2]));
            float h3 = __bfloat162float(__float2bfloat16(hn[3]));
            uint2 HV, LV;
            HV.x = pk2(hn[0], hn[1]); HV.y = pk2(hn[2], hn[3]);
            LV.x = pk2(hn[0] - h0, hn[1] - h1); LV.y = pk2(hn[2] - h2, hn[3] - h3);
            __stcg(reinterpret_cast<uint2*>(&g_hh[s & 1][g][er][slice * 16 + u0]), HV);
            __stcg(reinterpret_cast<uint2*>(&g_hl[s & 1][g][er][slice * 16 + u0]), LV);
        }
        __syncthreads();

        // ======== group barrier (16 slice-CTAs of this batch group) ========
        if (tid == 0) {
            __threadfence();
            int prev = atomicAdd(&g_bar_count[g], 1);
            if (prev == NSLICE - 1) {
                atomicExch(&g_bar_count[g], 0);
                __threadfence();
                atomicExch(&g_bar_sense[g], sense);
            } else {
                volatile int* sp = &g_bar_sense[g];
                while (*sp != sense) __nanosleep(32);
                __threadfence();
            }
        }
        __syncthreads();
        sense ^= 1;
    }

    // ---- final projection: out = h_n @ W_out^T + b_out (slice 0 only) ----
    if (slice == 0) {
        const int buf = (SEQ - 1) & 1;
        const float bo = b_out[0];
        for (int r8 = 0; r8 < 8; ++r8) {
            int r = wid * 8 + r8;
            int c0 = lane * 8;
            uint4 hv = __ldcg(reinterpret_cast<const uint4*>(&g_hh[buf][g][r][c0]));
            uint4 lv = __ldcg(reinterpret_cast<const uint4*>(&g_hl[buf][g][r][c0]));
            float acc = 0.0f;
            const uint32_t* hp = &hv.x;
            const uint32_t* lp = &lv.x;
            #pragma unroll
            for (int q = 0; q < 4; ++q) {
                float2 h2 = __bfloat1622float2(*reinterpret_cast<const __nv_bfloat162*>(&hp[q]));
                float2 l2 = __bfloat1622float2(*reinterpret_cast<const __nv_bfloat162*>(&lp[q]));
                acc += (h2.x + l2.x) * W_out[c0 + 2 * q]
                     + (h2.y + l2.y) * W_out[c0 + 2 * q + 1];
            }
            #pragma unroll
            for (int off = 16; off > 0; off >>= 1)
                acc += __shfl_xor_sync(0xFFFFFFFFu, acc, off);
            if (lane == 0) out[g * MR + r] = acc + bo;
        }
    }
}

// ---------------------------------------------------------------------------
extern "C" void kernel_launch(void* const* d_in, const int* in_sizes, int n_in,
                              void* d_out, int out_size) {
    const float* x     = (const float*)d_in[0];
    const float* W_ih  = (const float*)d_in[1];
    const float* W_hh  = (const float*)d_in[2];
    const float* b_ih  = (const float*)d_in[3];
    const float* b_hh  = (const float*)d_in[4];
    const float* W_out = (const float*)d_in[5];
    const float* b_out = (const float*)d_in[6];
    float* out = (float*)d_out;

    prep_x<<<2048, 256>>>(x);
    cudaFuncSetAttribute(lstm_mma,
                         cudaFuncAttributeMaxDynamicSharedMemorySize, SMEM_BYTES);
    lstm_mma<<<NCTA, NTHR, SMEM_BYTES>>>(W_ih, W_hh, b_ih, b_hh,
                                         W_out, b_out, out);
}

// round 7
// speedup vs baseline: 2.0053x; 1.1463x over previous
#include <cuda_runtime.h>
#include <cuda_bf16.h>
#include <cstdint>

// ---------------------------------------------------------------------------
// LSTM via warp-level mma.sync bf16 (fp32 accum), bf16-split fp32 emulation,
// software-pipelined step:
//   P1 x-part MMAs (kt0-7, no h dependence)  -- hides group-barrier latency
//   P2 barrier wait for h(s-1)
//   P3 cp.async h(s-1) [group H] + prefetch x[s+2-ish] [group X]
//   P4 wait H; P5 h-part MMAs (kt8-23); P6 frags->gsm (+wait X)
//   P7 epilogue (cell update, publish h); P8 sync + barrier arrive
// Grid: 8 batch groups (M=64) x 16 slices (N=64) = 128 CTAs, 1/SM.
// ---------------------------------------------------------------------------

#define SEQ     512
#define BATCH   512
#define INPUT   128
#define HIDDEN  256
#define NGROUP  8
#define NSLICE  16
#define NCTA    128
#define NTHR    256
#define MR      64
#define NC      64
#define KTOT    384

#define PITCH   784
#define AHI     0
#define ALO     50176
#define BHI     100352
#define BLO     150528
#define GSMO    200704
#define GPITCH  72
#define SMEM_BYTES 219136

__device__ __align__(16) __nv_bfloat16 g_xhi[SEQ * BATCH * INPUT];
__device__ __align__(16) __nv_bfloat16 g_xlo[SEQ * BATCH * INPUT];
__device__ __align__(16) __nv_bfloat16 g_hh[2][NGROUP][MR][HIDDEN];
__device__ __align__(16) __nv_bfloat16 g_hl[2][NGROUP][MR][HIDDEN];
__device__ int g_bar_count[NGROUP];
__device__ int g_bar_sense[NGROUP];

// ---------------------------------------------------------------------------
__device__ __forceinline__ uint32_t smem_u32(const void* p) {
    uint32_t a;
    asm("{ .reg .u64 t; cvta.to.shared.u64 t, %1; cvt.u32.u64 %0, t; }"
        : "=r"(a) : "l"(p));
    return a;
}
__device__ __forceinline__ void ldsm4(uint32_t* r, uint32_t addr) {
    asm volatile("ldmatrix.sync.aligned.m8n8.x4.shared.b16 {%0,%1,%2,%3}, [%4];"
        : "=r"(r[0]), "=r"(r[1]), "=r"(r[2]), "=r"(r[3]) : "r"(addr));
}
__device__ __forceinline__ void ldsm2(uint32_t* r, uint32_t addr) {
    asm volatile("ldmatrix.sync.aligned.m8n8.x2.shared.b16 {%0,%1}, [%2];"
        : "=r"(r[0]), "=r"(r[1]) : "r"(addr));
}
__device__ __forceinline__ void mma_bf16(float* d, const uint32_t* a,
                                         const uint32_t* b) {
    asm volatile("mma.sync.aligned.m16n8k16.row.col.f32.bf16.bf16.f32 "
        "{%0,%1,%2,%3}, {%4,%5,%6,%7}, {%8,%9}, {%0,%1,%2,%3};"
        : "+f"(d[0]), "+f"(d[1]), "+f"(d[2]), "+f"(d[3])
        : "r"(a[0]), "r"(a[1]), "r"(a[2]), "r"(a[3]), "r"(b[0]), "r"(b[1]));
}
__device__ __forceinline__ void cpasync16(uint32_t dst, const void* src) {
    asm volatile("cp.async.cg.shared.global [%0], [%1], 16;"
        :: "r"(dst), "l"(src));
}
#define CP_COMMIT() asm volatile("cp.async.commit_group;" ::: "memory")
#define CP_WAIT0()  asm volatile("cp.async.wait_group 0;" ::: "memory")
#define CP_WAIT1()  asm volatile("cp.async.wait_group 1;" ::: "memory")

__device__ __forceinline__ float sigf(float v)  { return 1.0f / (1.0f + __expf(-v)); }
__device__ __forceinline__ float tanhx(float v) { return 2.0f / (1.0f + __expf(-2.0f * v)) - 1.0f; }
__device__ __forceinline__ uint32_t pk2(float a, float b) {
    __nv_bfloat162 t = __floats2bfloat162_rn(a, b);
    return *reinterpret_cast<uint32_t*>(&t);
}

// ---------------------------------------------------------------------------
__global__ void prep_x(const float* __restrict__ x) {
    const int N4 = SEQ * BATCH * INPUT / 4;
    for (int i = blockIdx.x * blockDim.x + threadIdx.x; i < N4;
         i += gridDim.x * blockDim.x) {
        float4 v = *reinterpret_cast<const float4*>(x + 4 * i);
        float hx = __bfloat162float(__float2bfloat16(v.x));
        float hy = __bfloat162float(__float2bfloat16(v.y));
        float hz = __bfloat162float(__float2bfloat16(v.z));
        float hw = __bfloat162float(__float2bfloat16(v.w));
        uint2 hi, lo;
        hi.x = pk2(v.x, v.y); hi.y = pk2(v.z, v.w);
        lo.x = pk2(v.x - hx, v.y - hy); lo.y = pk2(v.z - hz, v.w - hw);
        reinterpret_cast<uint2*>(g_xhi)[i] = hi;
        reinterpret_cast<uint2*>(g_xlo)[i] = lo;
    }
}

// ---------------------------------------------------------------------------
__global__ void __launch_bounds__(NTHR, 1)
lstm_mma(const float* __restrict__ W_ih, const float* __restrict__ W_hh,
         const float* __restrict__ b_ih, const float* __restrict__ b_hh,
         const float* __restrict__ W_out, const float* __restrict__ b_out,
         float* __restrict__ out) {
    extern __shared__ char smem[];
    const uint32_t sA = smem_u32(smem);
    float* gsmf = reinterpret_cast<float*>(smem + GSMO);

    const int tid  = threadIdx.x;
    const int wid  = tid >> 5;
    const int lane = tid & 31;
    const int g     = blockIdx.x >> 4;
    const int slice = blockIdx.x & 15;
    const int mq = wid & 1;
    const int nq = wid >> 1;

    // ---- build B hi/lo in smem + zero A planes ----
    for (int i = tid; i < NC * KTOT; i += NTHR) {
        int n = i / KTOT, k = i - n * KTOT;
        int gcol = (n >> 4) * HIDDEN + slice * 16 + (n & 15);
        float wv = (k < INPUT) ? W_ih[(size_t)gcol * INPUT + k]
                               : W_hh[(size_t)gcol * HIDDEN + (k - INPUT)];
        __nv_bfloat16 bhh = __float2bfloat16(wv);
        __nv_bfloat16 bll = __float2bfloat16(wv - __bfloat162float(bhh));
        *reinterpret_cast<__nv_bfloat16*>(smem + BHI + n * PITCH + 2 * k) = bhh;
        *reinterpret_cast<__nv_bfloat16*>(smem + BLO + n * PITCH + 2 * k) = bll;
    }
    for (int i = tid; i < 2 * ALO / 4; i += NTHR)
        reinterpret_cast<uint32_t*>(smem + AHI)[i] = 0;
    __syncthreads();

    // ---- ldmatrix lane addresses ----
    const int l15 = lane & 15;
    const uint32_t aHi = sA + AHI + (uint32_t)(32 * mq + (lane & 15)) * PITCH
                       + (uint32_t)(lane >> 4) * 16;
    const uint32_t aLo = aHi + (ALO - AHI);
    const uint32_t bHiA = sA + BHI + (uint32_t)(16 * nq + (l15 & 7)) * PITCH
                        + (uint32_t)((l15 >> 3) & 1) * 16;
    const uint32_t bLoA = bHiA + (BLO - BHI);

    // ---- B_hi resident in registers ----
    uint32_t bh[24][2][2];
    #pragma unroll
    for (int kt = 0; kt < 24; ++kt) {
        ldsm2(&bh[kt][0][0], bHiA + kt * 32);
        ldsm2(&bh[kt][1][0], bHiA + 8 * PITCH + kt * 32);
    }

    // ---- stage x[0] ----
    {
        const __nv_bfloat16* xh_ = g_xhi + (size_t)(g * MR) * INPUT;
        const __nv_bfloat16* xl_ = g_xlo + (size_t)(g * MR) * INPUT;
        for (int i = tid; i < MR * 16; i += NTHR) {
            int r = i >> 4, ch = i & 15;
            uint32_t dst = sA + AHI + r * PITCH + ch * 16;
            cpasync16(dst, xh_ + r * INPUT + ch * 8);
            cpasync16(dst + (ALO - AHI), xl_ + r * INPUT + ch * 8);
        }
        CP_COMMIT();
        CP_WAIT0();
    }
    __syncthreads();

    // ---- bias C init ----
    float cb[2][2];
    #pragma unroll
    for (int nt = 0; nt < 2; ++nt) {
        int c0 = 16 * nq + 8 * nt + 2 * (lane & 3);
        int gc0 = (c0 >> 4) * HIDDEN + slice * 16 + (c0 & 15);
        int c1 = c0 + 1;
        int gc1 = (c1 >> 4) * HIDDEN + slice * 16 + (c1 & 15);
        cb[nt][0] = b_ih[gc0] + b_hh[gc0];
        cb[nt][1] = b_ih[gc1] + b_hh[gc1];
    }

    const int er = tid >> 2;
    const int u0 = (tid & 3) * 4;
    float cst[4] = {0.f, 0.f, 0.f, 0.f};

    for (int s = 0; s < SEQ; ++s) {
        // ===== P1: x-part MMAs (kt 0..7) — independent of h(s-1) =====
        float d[2][2][4];
        #pragma unroll
        for (int mt = 0; mt < 2; ++mt)
            #pragma unroll
            for (int nt = 0; nt < 2; ++nt) {
                d[mt][nt][0] = cb[nt][0]; d[mt][nt][1] = cb[nt][1];
                d[mt][nt][2] = cb[nt][0]; d[mt][nt][3] = cb[nt][1];
            }
        #pragma unroll
        for (int kt = 0; kt < 8; ++kt) {
            uint32_t ah0[4], ah1[4], al0[4], al1[4], bl0[2], bl1[2];
            ldsm4(ah0, aHi + kt * 32);
            ldsm4(ah1, aHi + 16 * PITCH + kt * 32);
            ldsm4(al0, aLo + kt * 32);
            ldsm4(al1, aLo + 16 * PITCH + kt * 32);
            ldsm2(bl0, bLoA + kt * 32);
            ldsm2(bl1, bLoA + 8 * PITCH + kt * 32);
            mma_bf16(d[0][0], ah0, bh[kt][0]); mma_bf16(d[0][1], ah0, bh[kt][1]);
            mma_bf16(d[1][0], ah1, bh[kt][0]); mma_bf16(d[1][1], ah1, bh[kt][1]);
            mma_bf16(d[0][0], al0, bh[kt][0]); mma_bf16(d[0][1], al0, bh[kt][1]);
            mma_bf16(d[1][0], al1, bh[kt][0]); mma_bf16(d[1][1], al1, bh[kt][1]);
            mma_bf16(d[0][0], ah0, bl0); mma_bf16(d[0][1], ah0, bl1);
            mma_bf16(d[1][0], ah1, bl0); mma_bf16(d[1][1], ah1, bl1);
        }

        // ===== P2: wait group barrier for h(s-1) =====
        if (s > 0 && tid == 0) {
            volatile int* sp = &g_bar_sense[g];
            int tgt = s & 1;
            while (*sp != tgt) __nanosleep(32);
            __threadfence();
        }
        __syncthreads();

        // ===== P3: cp.async h(s-1) [group H] + prefetch x[s+1] [group X] ====
        if (s > 0) {
            const __nv_bfloat16* hh = &g_hh[(s - 1) & 1][g][0][0];
            const __nv_bfloat16* hl = &g_hl[(s - 1) & 1][g][0][0];
            for (int i = tid; i < MR * 32; i += NTHR) {
                int r = i >> 5, ch = i & 31;
                uint32_t dst = sA + AHI + r * PITCH + 256 + ch * 16;
                cpasync16(dst, hh + r * HIDDEN + ch * 8);
                cpasync16(dst + (ALO - AHI), hl + r * HIDDEN + ch * 8);
            }
        }
        CP_COMMIT();                    // group H (maybe empty)
        if (s + 1 < SEQ) {
            const __nv_bfloat16* xh_ = g_xhi + ((size_t)(s + 1) * BATCH + g * MR) * INPUT;
            const __nv_bfloat16* xl_ = g_xlo + ((size_t)(s + 1) * BATCH + g * MR) * INPUT;
            for (int i = tid; i < MR * 16; i += NTHR) {
                int r = i >> 4, ch = i & 15;
                uint32_t dst = sA + AHI + r * PITCH + ch * 16;
                cpasync16(dst, xh_ + r * INPUT + ch * 8);
                cpasync16(dst + (ALO - AHI), xl_ + r * INPUT + ch * 8);
            }
        }
        CP_COMMIT();                    // group X (maybe empty)

        // ===== P4: wait H =====
        CP_WAIT1();
        __syncthreads();

        // ===== P5: h-part MMAs (kt 8..23) =====
        #pragma unroll
        for (int kt = 8; kt < 24; ++kt) {
            uint32_t ah0[4], ah1[4], al0[4], al1[4], bl0[2], bl1[2];
            ldsm4(ah0, aHi + kt * 32);
            ldsm4(ah1, aHi + 16 * PITCH + kt * 32);
            ldsm4(al0, aLo + kt * 32);
            ldsm4(al1, aLo + 16 * PITCH + kt * 32);
            ldsm2(bl0, bLoA + kt * 32);
            ldsm2(bl1, bLoA + 8 * PITCH + kt * 32);
            mma_bf16(d[0][0], ah0, bh[kt][0]); mma_bf16(d[0][1], ah0, bh[kt][1]);
            mma_bf16(d[1][0], ah1, bh[kt][0]); mma_bf16(d[1][1], ah1, bh[kt][1]);
            mma_bf16(d[0][0], al0, bh[kt][0]); mma_bf16(d[0][1], al0, bh[kt][1]);
            mma_bf16(d[1][0], al1, bh[kt][0]); mma_bf16(d[1][1], al1, bh[kt][1]);
            mma_bf16(d[0][0], ah0, bl0); mma_bf16(d[0][1], ah0, bl1);
            mma_bf16(d[1][0], ah1, bl0); mma_bf16(d[1][1], ah1, bl1);
        }

        // ===== P6: frags -> gsm; drain X =====
        #pragma unroll
        for (int mt = 0; mt < 2; ++mt)
            #pragma unroll
            for (int nt = 0; nt < 2; ++nt) {
                int r0 = 32 * mq + 16 * mt + (lane >> 2);
                int c0 = 16 * nq + 8 * nt + 2 * (lane & 3);
                *reinterpret_cast<float2*>(&gsmf[r0 * GPITCH + c0]) =
                    make_float2(d[mt][nt][0], d[mt][nt][1]);
                *reinterpret_cast<float2*>(&gsmf[(r0 + 8) * GPITCH + c0]) =
                    make_float2(d[mt][nt][2], d[mt][nt][3]);
            }
        CP_WAIT0();
        __syncthreads();

        // ===== P7: epilogue — cell update + publish h(s) =====
        {
            float4 gi = *reinterpret_cast<const float4*>(&gsmf[er * GPITCH +  0 + u0]);
            float4 gf = *reinterpret_cast<const float4*>(&gsmf[er * GPITCH + 16 + u0]);
            float4 gg = *reinterpret_cast<const float4*>(&gsmf[er * GPITCH + 32 + u0]);
            float4 go = *reinterpret_cast<const float4*>(&gsmf[er * GPITCH + 48 + u0]);
            float hn[4];
            cst[0] = sigf(gf.x) * cst[0] + sigf(gi.x) * tanhx(gg.x);
            cst[1] = sigf(gf.y) * cst[1] + sigf(gi.y) * tanhx(gg.y);
            cst[2] = sigf(gf.z) * cst[2] + sigf(gi.z) * tanhx(gg.z);
            cst[3] = sigf(gf.w) * cst[3] + sigf(gi.w) * tanhx(gg.w);
            hn[0] = sigf(go.x) * tanhx(cst[0]);
            hn[1] = sigf(go.y) * tanhx(cst[1]);
            hn[2] = sigf(go.z) * tanhx(cst[2]);
            hn[3] = sigf(go.w) * tanhx(cst[3]);
            float h0 = __bfloat162float(__float2bfloat16(hn[0]));
            float h1 = __bfloat162float(__float2bfloat16(hn[1]));
            float h2 = __bfloat162float(__float2bfloat16(hn[2]));
            float h3 = __bfloat162float(__float2bfloat16(hn[3]));
            uint2 HV, LV;
            HV.x = pk2(hn[0], hn[1]); HV.y = pk2(hn[2], hn[3]);
            LV.x = pk2(hn[0] - h0, hn[1] - h1); LV.y = pk2(hn[2] - h2, hn[3] - h3);
            __stcg(reinterpret_cast<uint2*>(&g_hh[s & 1][g][er][slice * 16 + u0]), HV);
            __stcg(reinterpret_cast<uint2*>(&g_hl[s & 1][g][er][slice * 16 + u0]), LV);
        }

        // ===== P8: sync + barrier arrive (round s, sense (s&1)^1) =====
        __syncthreads();
        if (tid == 0) {
            __threadfence();
            int prev = atomicAdd(&g_bar_count[g], 1);
            if (prev == NSLICE - 1) {
                atomicExch(&g_bar_count[g], 0);
                __threadfence();
                atomicExch(&g_bar_sense[g], (s & 1) ^ 1);
            }
        }
    }

    // ---- final barrier wait (round SEQ-1, sense ((SEQ-1)&1)^1 = 0) ----
    if (tid == 0) {
        volatile int* sp = &g_bar_sense[g];
        while (*sp != 0) __nanosleep(32);
        __threadfence();
    }
    __syncthreads();

    // ---- final projection (slice 0): out = h_n @ W_out^T + b_out ----
    if (slice == 0) {
        const int buf = (SEQ - 1) & 1;
        const float bo = b_out[0];
        for (int r8 = 0; r8 < 8; ++r8) {
            int r = wid * 8 + r8;
            int c0 = lane * 8;
            uint4 hv = __ldcg(reinterpret_cast<const uint4*>(&g_hh[buf][g][r][c0]));
            uint4 lv = __ldcg(reinterpret_cast<const uint4*>(&g_hl[buf][g][r][c0]));
            float acc = 0.0f;
            const uint32_t* hp = &hv.x;
            const uint32_t* lp = &lv.x;
            #pragma unroll
            for (int q = 0; q < 4; ++q) {
                float2 h2 = __bfloat1622float2(*reinterpret_cast<const __nv_bfloat162*>(&hp[q]));
                float2 l2 = __bfloat1622float2(*reinterpret_cast<const __nv_bfloat162*>(&lp[q]));
                acc += (h2.x + l2.x) * W_out[c0 + 2 * q]
                     + (h2.y + l2.y) * W_out[c0 + 2 * q + 1];
            }
            #pragma unroll
            for (int off = 16; off > 0; off >>= 1)
                acc += __shfl_xor_sync(0xFFFFFFFFu, acc, off);
            if (lane == 0) out[g * MR + r] = acc + bo;
        }
    }
}

// ---------------------------------------------------------------------------
extern "C" void kernel_launch(void* const* d_in, const int* in_sizes, int n_in,
                              void* d_out, int out_size) {
    const float* x     = (const float*)d_in[0];
    const float* W_ih  = (const float*)d_in[1];
    const float* W_hh  = (const float*)d_in[2];
    const float* b_ih  = (const float*)d_in[3];
    const float* b_hh  = (const float*)d_in[4];
    const float* W_out = (const float*)d_in[5];
    const float* b_out = (const float*)d_in[6];
    float* out = (float*)d_out;

    prep_x<<<2048, 256>>>(x);
    cudaFuncSetAttribute(lstm_mma,
                         cudaFuncAttributeMaxDynamicSharedMemorySize, SMEM_BYTES);
    lstm_mma<<<NCTA, NTHR, SMEM_BYTES>>>(W_ih, W_hh, b_ih, b_hh,
                                         W_out, b_out, out);
}

// round 8
// speedup vs baseline: 2.1419x; 1.0681x over previous
#include <cuda_runtime.h>
#include <cuda_bf16.h>
#include <cstdint>

// ---------------------------------------------------------------------------
// LSTM via warp-level mma.sync bf16 (fp32 accum), 3-pass bf16-split emulation.
// Round 8: regrouped 16 batch-groups (M=32) x 8 slices (N=128) = 128 CTAs;
// per-CTA h consumption 4x smaller; step reordered so x-part MMAs hide the
// cp.async h latency (issue copies first, compute x-MMAs over them).
// B_hi: 96 regs/warp (staged in 2 phases through aliased smem). B_lo: smem.
// x: double-buffered smem region, prefetched one step ahead.
// ---------------------------------------------------------------------------

#define SEQ     512
#define BATCH   512
#define INPUT   128
#define HIDDEN  256
#define NGROUP  16
#define NSLICE  8
#define NCTA    128
#define NTHR    256
#define MR      32          // batch rows per CTA
#define NC      128         // gate cols per CTA (4 gates x 32 units)
#define KTOT    384

// smem layout (bytes)
#define BPITCH  784
#define XPITCH  272
#define HPITCH  528
#define GPITCH  136         // floats
#define BLO_O   0           // 128*784      = 100352
#define AXHI_O  100352      // 2 bufs*32*272 = 17408
#define AXLO_O  117760
#define AHHI_O  135168      // 32*528 = 16896
#define AHLO_O  152064
#define GSM_O   168960      // 32*136*4 = 17408
#define SMEM_BYTES 186368
#define XBUF    8704        // one x buffer (32*272)

__device__ __align__(16) __nv_bfloat16 g_xhi[SEQ * BATCH * INPUT];
__device__ __align__(16) __nv_bfloat16 g_xlo[SEQ * BATCH * INPUT];
__device__ __align__(16) __nv_bfloat16 g_hh[2][NGROUP][MR][HIDDEN];
__device__ __align__(16) __nv_bfloat16 g_hl[2][NGROUP][MR][HIDDEN];
__device__ int g_bar_count[NGROUP];
__device__ int g_bar_sense[NGROUP];

// ---------------------------------------------------------------------------
__device__ __forceinline__ uint32_t smem_u32(const void* p) {
    uint32_t a;
    asm("{ .reg .u64 t; cvta.to.shared.u64 t, %1; cvt.u32.u64 %0, t; }"
        : "=r"(a) : "l"(p));
    return a;
}
__device__ __forceinline__ void ldsm4(uint32_t* r, uint32_t addr) {
    asm volatile("ldmatrix.sync.aligned.m8n8.x4.shared.b16 {%0,%1,%2,%3}, [%4];"
        : "=r"(r[0]), "=r"(r[1]), "=r"(r[2]), "=r"(r[3]) : "r"(addr));
}
__device__ __forceinline__ void ldsm2(uint32_t* r, uint32_t addr) {
    asm volatile("ldmatrix.sync.aligned.m8n8.x2.shared.b16 {%0,%1}, [%2];"
        : "=r"(r[0]), "=r"(r[1]) : "r"(addr));
}
__device__ __forceinline__ void mma_bf16(float* d, const uint32_t* a,
                                         const uint32_t* b) {
    asm volatile("mma.sync.aligned.m16n8k16.row.col.f32.bf16.bf16.f32 "
        "{%0,%1,%2,%3}, {%4,%5,%6,%7}, {%8,%9}, {%0,%1,%2,%3};"
        : "+f"(d[0]), "+f"(d[1]), "+f"(d[2]), "+f"(d[3])
        : "r"(a[0]), "r"(a[1]), "r"(a[2]), "r"(a[3]), "r"(b[0]), "r"(b[1]));
}
__device__ __forceinline__ void cpasync16(uint32_t dst, const void* src) {
    asm volatile("cp.async.cg.shared.global [%0], [%1], 16;"
        :: "r"(dst), "l"(src));
}
#define CP_COMMIT() asm volatile("cp.async.commit_group;" ::: "memory")
#define CP_WAIT0()  asm volatile("cp.async.wait_group 0;" ::: "memory")
#define CP_WAIT1()  asm volatile("cp.async.wait_group 1;" ::: "memory")

__device__ __forceinline__ float sigf(float v)  { return 1.0f / (1.0f + __expf(-v)); }
__device__ __forceinline__ float tanhx(float v) { return 2.0f / (1.0f + __expf(-2.0f * v)) - 1.0f; }
__device__ __forceinline__ uint32_t pk2(float a, float b) {
    __nv_bfloat162 t = __floats2bfloat162_rn(a, b);
    return *reinterpret_cast<uint32_t*>(&t);
}

// ---------------------------------------------------------------------------
__global__ void prep_x(const float* __restrict__ x) {
    const int N4 = SEQ * BATCH * INPUT / 4;
    for (int i = blockIdx.x * blockDim.x + threadIdx.x; i < N4;
         i += gridDim.x * blockDim.x) {
        float4 v = *reinterpret_cast<const float4*>(x + 4 * i);
        float hx = __bfloat162float(__float2bfloat16(v.x));
        float hy = __bfloat162float(__float2bfloat16(v.y));
        float hz = __bfloat162float(__float2bfloat16(v.z));
        float hw = __bfloat162float(__float2bfloat16(v.w));
        uint2 hi, lo;
        hi.x = pk2(v.x, v.y); hi.y = pk2(v.z, v.w);
        lo.x = pk2(v.x - hx, v.y - hy); lo.y = pk2(v.z - hz, v.w - hw);
        reinterpret_cast<uint2*>(g_xhi)[i] = hi;
        reinterpret_cast<uint2*>(g_xlo)[i] = lo;
    }
}

// ---------------------------------------------------------------------------
__global__ void __launch_bounds__(NTHR, 1)
lstm_mma(const float* __restrict__ W_ih, const float* __restrict__ W_hh,
         const float* __restrict__ b_ih, const float* __restrict__ b_hh,
         const float* __restrict__ W_out, const float* __restrict__ b_out,
         float* __restrict__ out) {
    extern __shared__ char smem[];
    const uint32_t sA = smem_u32(smem);
    float* gsmf = reinterpret_cast<float*>(smem + GSM_O);

    const int tid  = threadIdx.x;
    const int wid  = tid >> 5;
    const int lane = tid & 31;
    const int g     = blockIdx.x >> 3;   // batch group: rows g*32..g*32+31
    const int slice = blockIdx.x & 7;    // hidden units slice*32..slice*32+31
    const int nq = wid;                  // warp n-strip: cols 16*nq..16*nq+15
    const int l15 = lane & 15;

    // ---- build B_lo (full 128 cols) in smem ----
    // CTA-local col n: gate = n>>5, unit = n&31 -> gcol = gate*256+slice*32+unit
    for (int i = tid; i < NC * KTOT; i += NTHR) {
        int n = i / KTOT, k = i - n * KTOT;
        int gcol = (n >> 5) * HIDDEN + slice * 32 + (n & 31);
        float wv = (k < INPUT) ? W_ih[(size_t)gcol * INPUT + k]
                               : W_hh[(size_t)gcol * HIDDEN + (k - INPUT)];
        __nv_bfloat16 bhv = __float2bfloat16(wv);
        __nv_bfloat16 blv = __float2bfloat16(wv - __bfloat162float(bhv));
        *reinterpret_cast<__nv_bfloat16*>(smem + BLO_O + n * BPITCH + 2 * k) = blv;
    }

    // ---- B_hi -> registers, staged in 2 phases of 64 cols (alias at AXHI) --
    uint32_t bh[24][2][2];
    #pragma unroll
    for (int p = 0; p < 2; ++p) {
        __syncthreads();
        for (int i = tid; i < 64 * KTOT; i += NTHR) {
            int n = i / KTOT, k = i - n * KTOT;
            int gn = p * 64 + n;
            int gcol = (gn >> 5) * HIDDEN + slice * 32 + (gn & 31);
            float wv = (k < INPUT) ? W_ih[(size_t)gcol * INPUT + k]
                                   : W_hh[(size_t)gcol * HIDDEN + (k - INPUT)];
            *reinterpret_cast<__nv_bfloat16*>(smem + AXHI_O + n * BPITCH + 2 * k) =
                __float2bfloat16(wv);
        }
        __syncthreads();
        if ((nq >> 2) == p) {
            int nloc = 16 * (nq & 3);
            uint32_t base = sA + AXHI_O + (uint32_t)(nloc + (l15 & 7)) * BPITCH
                          + (uint32_t)((l15 >> 3) & 1) * 16;
            #pragma unroll
            for (int kt = 0; kt < 24; ++kt) {
                ldsm2(&bh[kt][0][0], base + kt * 32);
                ldsm2(&bh[kt][1][0], base + 8 * BPITCH + kt * 32);
            }
        }
    }
    __syncthreads();

    // ---- zero Ah planes (h=0 at step 0) ----
    for (int i = tid; i < (GSM_O - AHHI_O) / 4; i += NTHR)
        reinterpret_cast<uint32_t*>(smem + AHHI_O)[i] = 0;

    // ---- stage x[0] into x-buffer 0 ----
    {
        const __nv_bfloat16* xh_ = g_xhi + (size_t)(g * MR) * INPUT;
        const __nv_bfloat16* xl_ = g_xlo + (size_t)(g * MR) * INPUT;
        for (int i = tid; i < MR * 16; i += NTHR) {
            int r = i >> 4, ch = i & 15;
            uint32_t dst = sA + AXHI_O + r * XPITCH + ch * 16;
            cpasync16(dst, xh_ + r * INPUT + ch * 8);
            cpasync16(dst + (AXLO_O - AXHI_O), xl_ + r * INPUT + ch * 8);
        }
        CP_COMMIT();
        CP_WAIT0();
    }
    __syncthreads();

    // ---- ldmatrix per-lane bases ----
    const uint32_t baseX  = sA + AXHI_O + (uint32_t)l15 * XPITCH
                          + (uint32_t)(lane >> 4) * 16;
    const uint32_t baseH  = sA + AHHI_O + (uint32_t)l15 * HPITCH
                          + (uint32_t)(lane >> 4) * 16;
    const uint32_t baseBL = sA + BLO_O + (uint32_t)(16 * nq + (l15 & 7)) * BPITCH
                          + (uint32_t)((l15 >> 3) & 1) * 16;

    // ---- bias C init ----
    float cb[2][2];
    #pragma unroll
    for (int nt = 0; nt < 2; ++nt) {
        int c0 = 16 * nq + 8 * nt + 2 * (lane & 3);
        int gc0 = (c0 >> 5) * HIDDEN + slice * 32 + (c0 & 31);
        int c1 = c0 + 1;
        int gc1 = (c1 >> 5) * HIDDEN + slice * 32 + (c1 & 31);
        cb[nt][0] = b_ih[gc0] + b_hh[gc0];
        cb[nt][1] = b_ih[gc1] + b_hh[gc1];
    }

    const int er = tid >> 3;           // epilogue row 0..31
    const int u0 = (tid & 7) << 2;     // epilogue unit 0..28
    float cst[4] = {0.f, 0.f, 0.f, 0.f};

    for (int s = 0; s < SEQ; ++s) {
        // ===== P2: group barrier wait for h(s-1) =====
        if (s > 0 && tid == 0) {
            volatile int* sp = &g_bar_sense[g];
            int tgt = s & 1;
            while (*sp != tgt) __nanosleep(32);
            __threadfence();
        }
        __syncthreads();

        // ===== P3: issue cp.async h(s-1) [H] + prefetch x(s+1) [X] =====
        if (s > 0) {
            const __nv_bfloat16* hh = &g_hh[(s - 1) & 1][g][0][0];
            const __nv_bfloat16* hl = &g_hl[(s - 1) & 1][g][0][0];
            for (int i = tid; i < MR * 32; i += NTHR) {
                int r = i >> 5, ch = i & 31;
                uint32_t dst = sA + AHHI_O + r * HPITCH + ch * 16;
                cpasync16(dst, hh + r * HIDDEN + ch * 8);
                cpasync16(dst + (AHLO_O - AHHI_O), hl + r * HIDDEN + ch * 8);
            }
        }
        CP_COMMIT();                       // group H
        if (s + 1 < SEQ) {
            const __nv_bfloat16* xh_ = g_xhi + ((size_t)(s + 1) * BATCH + g * MR) * INPUT;
            const __nv_bfloat16* xl_ = g_xlo + ((size_t)(s + 1) * BATCH + g * MR) * INPUT;
            uint32_t xb = ((s + 1) & 1) * XBUF;
            for (int i = tid; i < MR * 16; i += NTHR) {
                int r = i >> 4, ch = i & 15;
                uint32_t dst = sA + AXHI_O + xb + r * XPITCH + ch * 16;
                cpasync16(dst, xh_ + r * INPUT + ch * 8);
                cpasync16(dst + (AXLO_O - AXHI_O), xl_ + r * INPUT + ch * 8);
            }
        }
        CP_COMMIT();                       // group X

        // ===== P1: x-part MMAs (kt 0..7) over in-flight copies =====
        float d[2][2][4];
        #pragma unroll
        for (int mt = 0; mt < 2; ++mt)
            #pragma unroll
            for (int nt = 0; nt < 2; ++nt) {
                d[mt][nt][0] = cb[nt][0]; d[mt][nt][1] = cb[nt][1];
                d[mt][nt][2] = cb[nt][0]; d[mt][nt][3] = cb[nt][1];
            }
        {
            uint32_t bx = baseX + (s & 1) * XBUF;
            #pragma unroll
            for (int kt = 0; kt < 8; ++kt) {
                uint32_t ah0[4], ah1[4], al0[4], al1[4], bl0[2], bl1[2];
                ldsm4(ah0, bx + kt * 32);
                ldsm4(ah1, bx + 16 * XPITCH + kt * 32);
                ldsm4(al0, bx + (AXLO_O - AXHI_O) + kt * 32);
                ldsm4(al1, bx + (AXLO_O - AXHI_O) + 16 * XPITCH + kt * 32);
                ldsm2(bl0, baseBL + kt * 32);
                ldsm2(bl1, baseBL + 8 * BPITCH + kt * 32);
                mma_bf16(d[0][0], ah0, bh[kt][0]); mma_bf16(d[0][1], ah0, bh[kt][1]);
                mma_bf16(d[1][0], ah1, bh[kt][0]); mma_bf16(d[1][1], ah1, bh[kt][1]);
                mma_bf16(d[0][0], al0, bh[kt][0]); mma_bf16(d[0][1], al0, bh[kt][1]);
                mma_bf16(d[1][0], al1, bh[kt][0]); mma_bf16(d[1][1], al1, bh[kt][1]);
                mma_bf16(d[0][0], ah0, bl0); mma_bf16(d[0][1], ah0, bl1);
                mma_bf16(d[1][0], ah1, bl0); mma_bf16(d[1][1], ah1, bl1);
            }
        }

        // ===== P4: wait H =====
        CP_WAIT1();
        __syncthreads();

        // ===== P5: h-part MMAs (kt 8..23) =====
        #pragma unroll
        for (int kt = 8; kt < 24; ++kt) {
            uint32_t ah0[4], ah1[4], al0[4], al1[4], bl0[2], bl1[2];
            uint32_t ko = (kt - 8) * 32;
            ldsm4(ah0, baseH + ko);
            ldsm4(ah1, baseH + 16 * HPITCH + ko);
            ldsm4(al0, baseH + (AHLO_O - AHHI_O) + ko);
            ldsm4(al1, baseH + (AHLO_O - AHHI_O) + 16 * HPITCH + ko);
            ldsm2(bl0, baseBL + kt * 32);
            ldsm2(bl1, baseBL + 8 * BPITCH + kt * 32);
            mma_bf16(d[0][0], ah0, bh[kt][0]); mma_bf16(d[0][1], ah0, bh[kt][1]);
            mma_bf16(d[1][0], ah1, bh[kt][0]); mma_bf16(d[1][1], ah1, bh[kt][1]);
            mma_bf16(d[0][0], al0, bh[kt][0]); mma_bf16(d[0][1], al0, bh[kt][1]);
            mma_bf16(d[1][0], al1, bh[kt][0]); mma_bf16(d[1][1], al1, bh[kt][1]);
            mma_bf16(d[0][0], ah0, bl0); mma_bf16(d[0][1], ah0, bl1);
            mma_bf16(d[1][0], ah1, bl0); mma_bf16(d[1][1], ah1, bl1);
        }

        // ===== P6: fragments -> gsm; drain X =====
        #pragma unroll
        for (int mt = 0; mt < 2; ++mt)
            #pragma unroll
            for (int nt = 0; nt < 2; ++nt) {
                int r0 = 16 * mt + (lane >> 2);
                int c0 = 16 * nq + 8 * nt + 2 * (lane & 3);
                *reinterpret_cast<float2*>(&gsmf[r0 * GPITCH + c0]) =
                    make_float2(d[mt][nt][0], d[mt][nt][1]);
                *reinterpret_cast<float2*>(&gsmf[(r0 + 8) * GPITCH + c0]) =
                    make_float2(d[mt][nt][2], d[mt][nt][3]);
            }
        CP_WAIT0();
        __syncthreads();

        // ===== P7: epilogue — cell update + publish h(s) =====
        {
            float4 gi = *reinterpret_cast<const float4*>(&gsmf[er * GPITCH +  0 + u0]);
            float4 gf = *reinterpret_cast<const float4*>(&gsmf[er * GPITCH + 32 + u0]);
            float4 gg = *reinterpret_cast<const float4*>(&gsmf[er * GPITCH + 64 + u0]);
            float4 go = *reinterpret_cast<const float4*>(&gsmf[er * GPITCH + 96 + u0]);
            float hn[4];
            cst[0] = sigf(gf.x) * cst[0] + sigf(gi.x) * tanhx(gg.x);
            cst[1] = sigf(gf.y) * cst[1] + sigf(gi.y) * tanhx(gg.y);
            cst[2] = sigf(gf.z) * cst[2] + sigf(gi.z) * tanhx(gg.z);
            cst[3] = sigf(gf.w) * cst[3] + sigf(gi.w) * tanhx(gg.w);
            hn[0] = sigf(go.x) * tanhx(cst[0]);
            hn[1] = sigf(go.y) * tanhx(cst[1]);
            hn[2] = sigf(go.z) * tanhx(cst[2]);
            hn[3] = sigf(go.w) * tanhx(cst[3]);
            float h0 = __bfloat162float(__float2bfloat16(hn[0]));
            float h1 = __bfloat162float(__float2bfloat16(hn[1]));
            float h2 = __bfloat162float(__float2bfloat16(hn[2]));
            float h3 = __bfloat162float(__float2bfloat16(hn[3]));
            uint2 HV, LV;
            HV.x = pk2(hn[0], hn[1]); HV.y = pk2(hn[2], hn[3]);
            LV.x = pk2(hn[0] - h0, hn[1] - h1); LV.y = pk2(hn[2] - h2, hn[3] - h3);
            __stcg(reinterpret_cast<uint2*>(&g_hh[s & 1][g][er][slice * 32 + u0]), HV);
            __stcg(reinterpret_cast<uint2*>(&g_hl[s & 1][g][er][slice * 32 + u0]), LV);
        }

        // ===== P8: sync + barrier arrive =====
        __syncthreads();
        if (tid == 0) {
            __threadfence();
            int prev = atomicAdd(&g_bar_count[g], 1);
            if (prev == NSLICE - 1) {
                atomicExch(&g_bar_count[g], 0);
                __threadfence();
                atomicExch(&g_bar_sense[g], (s & 1) ^ 1);
            }
        }
    }

    // ---- final barrier wait (round 511 sets sense 0) ----
    if (tid == 0) {
        volatile int* sp = &g_bar_sense[g];
        while (*sp != 0) __nanosleep(32);
        __threadfence();
    }
    __syncthreads();

    // ---- final projection (slice 0): out = h_n @ W_out^T + b_out ----
    if (slice == 0) {
        const int buf = (SEQ - 1) & 1;
        const float bo = b_out[0];
        for (int r4 = 0; r4 < 4; ++r4) {
            int r = wid * 4 + r4;
            int c0 = lane * 8;
            uint4 hv = __ldcg(reinterpret_cast<const uint4*>(&g_hh[buf][g][r][c0]));
            uint4 lv = __ldcg(reinterpret_cast<const uint4*>(&g_hl[buf][g][r][c0]));
            float acc = 0.0f;
            const uint32_t* hp = &hv.x;
            const uint32_t* lp = &lv.x;
            #pragma unroll
            for (int q = 0; q < 4; ++q) {
                float2 h2 = __bfloat1622float2(*reinterpret_cast<const __nv_bfloat162*>(&hp[q]));
                float2 l2 = __bfloat1622float2(*reinterpret_cast<const __nv_bfloat162*>(&lp[q]));
                acc += (h2.x + l2.x) * W_out[c0 + 2 * q]
                     + (h2.y + l2.y) * W_out[c0 + 2 * q + 1];
            }
            #pragma unroll
            for (int off = 16; off > 0; off >>= 1)
                acc += __shfl_xor_sync(0xFFFFFFFFu, acc, off);
            if (lane == 0) out[g * MR + r] = acc + bo;
        }
    }
}

// ---------------------------------------------------------------------------
extern "C" void kernel_launch(void* const* d_in, const int* in_sizes, int n_in,
                              void* d_out, int out_size) {
    const float* x     = (const float*)d_in[0];
    const float* W_ih  = (const float*)d_in[1];
    const float* W_hh  = (const float*)d_in[2];
    const float* b_ih  = (const float*)d_in[3];
    const float* b_hh  = (const float*)d_in[4];
    const float* W_out = (const float*)d_in[5];
    const float* b_out = (const float*)d_in[6];
    float* out = (float*)d_out;

    prep_x<<<2048, 256>>>(x);
    cudaFuncSetAttribute(lstm_mma,
                         cudaFuncAttributeMaxDynamicSharedMemorySize, SMEM_BYTES);
    lstm_mma<<<NCTA, NTHR, SMEM_BYTES>>>(W_ih, W_hh, b_ih, b_hh,
                                         W_out, b_out, out);
}